// round 11
// baseline (speedup 1.0000x reference)
#include <cuda_runtime.h>
#include <cuda_bf16.h>
#include <math.h>

#define T_STEPS 128
#define NE 64
#define NA 8
#define OBS 64
#define D 128
#define CH 128
#define VH 256
#define BATCH 512           // NE*NA
#define TB (T_STEPS*BATCH)  // 65536
#define ITERS 2

// ---------------- scratch (static device arrays: allocation-free) -------------
__device__ float g_gi[TB * 3 * D];
__device__ float g_e[TB * D];
__device__ float g_ctx[TB * D];
__device__ unsigned char g_dmask[TB];
__device__ int g_dflag;   // 0 = uint8/bool, 1 = float32, 2 = int32

// ---------------- dones dtype detection + canonicalization --------------------
__global__ void detect_dones_kernel(const unsigned char* __restrict__ p, int n)
{
    __shared__ int s_nonbin, s_off4;
    if (threadIdx.x == 0) { s_nonbin = 0; s_off4 = 0; }
    __syncthreads();
    int nb = 0, o4 = 0;
    for (int i = threadIdx.x; i < n; i += blockDim.x) {
        const unsigned char b = p[i];
        if (b > 1) nb = 1;
        else if (b == 1 && (i & 3)) o4 = 1;
    }
    if (nb) atomicOr(&s_nonbin, 1);
    if (o4) atomicOr(&s_off4, 1);
    __syncthreads();
    if (threadIdx.x == 0)
        g_dflag = s_nonbin ? 1 : (s_off4 ? 0 : 2);
}

__global__ void conv_dones_kernel(const void* __restrict__ p, int n)
{
    const int i = blockIdx.x * blockDim.x + threadIdx.x;
    if (i >= n) return;
    const int f = g_dflag;
    unsigned char m;
    if (f == 1)      m = (((const float*)p)[i] != 0.f);
    else if (f == 2) m = (((const int*)p)[i] != 0);
    else             m = (((const unsigned char*)p)[i] != 0);
    g_dmask[i] = m;
}

// ================= bf16 3-product GEMM building blocks =========================
#define BST 136     // B-tile row stride (u32)
#define AST 12      // A-ring row stride (u32)
#define IST 68      // intermediate row stride, K=128 (64 pairs + 4 pad)
#define IST2 132    // intermediate row stride, K=256 (128 pairs + 4 pad)
#define ABUF (128*AST)
#define BBUF (8*BST)

#define ZERO_ACC(acc) do {                                           \
    _Pragma("unroll") for (int _i = 0; _i < 4; _i++)                  \
    _Pragma("unroll") for (int _j = 0; _j < 4; _j++)                  \
    _Pragma("unroll") for (int _q = 0; _q < 4; _q++)                  \
        acc[_i][_j][_q] = 0.f;                                        \
} while (0)

__device__ __forceinline__ unsigned pack_bf16(float lo_elem, float hi_elem)
{
    unsigned d;
    asm("cvt.rn.bf16x2.f32 %0, %1, %2;" : "=r"(d) : "f"(hi_elem), "f"(lo_elem));
    return d;
}

__device__ __forceinline__ float bf16hi(float x)
{
    return __bfloat162float(__float2bfloat16(x));
}

__device__ __forceinline__ void mma_bf16(float* c, const unsigned* a, const unsigned* b)
{
    asm volatile(
        "mma.sync.aligned.m16n8k16.row.col.f32.bf16.bf16.f32 "
        "{%0,%1,%2,%3}, {%4,%5,%6,%7}, {%8,%9}, {%0,%1,%2,%3};"
        : "+f"(c[0]), "+f"(c[1]), "+f"(c[2]), "+f"(c[3])
        : "r"(a[0]), "r"(a[1]), "r"(a[2]), "r"(a[3]), "r"(b[0]), "r"(b[1]));
}

// one k16 chunk of mma over the 128x128 block tile
__device__ __forceinline__ void mma_chunk(
    const unsigned* __restrict__ Ah, const unsigned* __restrict__ Al, int ast, int kb,
    const unsigned* __restrict__ Bh, const unsigned* __restrict__ Bl,
    float acc[4][4][4], int tid)
{
    const int lane = tid & 31, w = tid >> 5;
    const int gid = lane >> 2, tig = lane & 3;
    const int wm = (w & 1) * 64, wn = (w >> 1) * 32;
    unsigned bh[4][2], bl[4][2];
#pragma unroll
    for (int ns = 0; ns < 4; ns++) {
        const int n = wn + ns * 8 + gid;
        bh[ns][0] = Bh[tig * BST + n];       bh[ns][1] = Bh[(tig + 4) * BST + n];
        bl[ns][0] = Bl[tig * BST + n];       bl[ns][1] = Bl[(tig + 4) * BST + n];
    }
#pragma unroll
    for (int ms = 0; ms < 4; ms++) {
        const int m0 = wm + ms * 16 + gid;
        unsigned ah[4], al[4];
        ah[0] = Ah[m0 * ast + kb + tig];       ah[1] = Ah[(m0 + 8) * ast + kb + tig];
        ah[2] = Ah[m0 * ast + kb + tig + 4];   ah[3] = Ah[(m0 + 8) * ast + kb + tig + 4];
        al[0] = Al[m0 * ast + kb + tig];       al[1] = Al[(m0 + 8) * ast + kb + tig];
        al[2] = Al[m0 * ast + kb + tig + 4];   al[3] = Al[(m0 + 8) * ast + kb + tig + 4];
#pragma unroll
        for (int ns = 0; ns < 4; ns++) {
            mma_bf16(acc[ms][ns], ah, bh[ns]);   // hi*hi
            mma_bf16(acc[ms][ns], ah, bl[ns]);   // hi*lo
            mma_bf16(acc[ms][ns], al, bh[ns]);   // lo*hi
        }
    }
}

// B ring: fetch + stage (hi/lo split, k-pair packed)
__device__ __forceinline__ void b_fetch(const float* __restrict__ B, int ldb, int k0, int bc,
                                        int tid, float4& r0, float4& r1)
{
    const int brw = tid >> 5, bfc = (tid & 31) * 4;
    r0 = *(const float4*)(B + (size_t)(k0 + 2 * brw) * ldb + bc + bfc);
    r1 = *(const float4*)(B + (size_t)(k0 + 2 * brw + 1) * ldb + bc + bfc);
}

__device__ __forceinline__ void b_stage(unsigned* Bh, unsigned* Bl, int tid,
                                        const float4& va, const float4& vb)
{
    const int base = (tid >> 5) * BST + (tid & 31) * 4;
    const float ha0 = bf16hi(va.x), ha1 = bf16hi(va.y), ha2 = bf16hi(va.z), ha3 = bf16hi(va.w);
    const float hb0 = bf16hi(vb.x), hb1 = bf16hi(vb.y), hb2 = bf16hi(vb.z), hb3 = bf16hi(vb.w);
    *(uint4*)&Bh[base] = make_uint4(pack_bf16(ha0, hb0), pack_bf16(ha1, hb1),
                                    pack_bf16(ha2, hb2), pack_bf16(ha3, hb3));
    *(uint4*)&Bl[base] = make_uint4(pack_bf16(va.x - ha0, vb.x - hb0), pack_bf16(va.y - ha1, vb.y - hb1),
                                    pack_bf16(va.z - ha2, vb.z - hb2), pack_bf16(va.w - ha3, vb.w - hb3));
}

// A ring (gmem A): fetch + stage
__device__ __forceinline__ void a_fetch(const float* __restrict__ A, int lda, int brow, int k0,
                                        int tid, float4& r0, float4& r1)
{
    const int arow0 = tid >> 2, afc = (tid & 3) * 4;
    r0 = *(const float4*)(A + (size_t)(brow + arow0) * lda + k0 + afc);
    r1 = *(const float4*)(A + (size_t)(brow + arow0 + 64) * lda + k0 + afc);
}

__device__ __forceinline__ void a_stage(unsigned* Ah, unsigned* Al, int tid,
                                        const float4& v0, const float4& v1)
{
    const int arow0 = tid >> 2;
    const int kb = (tid & 3) * 2;
    {
        const float4 v = v0;
        const float h0 = bf16hi(v.x), h1 = bf16hi(v.y), h2 = bf16hi(v.z), h3 = bf16hi(v.w);
        *(uint2*)&Ah[arow0 * AST + kb] = make_uint2(pack_bf16(h0, h1), pack_bf16(h2, h3));
        *(uint2*)&Al[arow0 * AST + kb] = make_uint2(pack_bf16(v.x - h0, v.y - h1),
                                                    pack_bf16(v.z - h2, v.w - h3));
    }
    {
        const float4 v = v1;
        const float h0 = bf16hi(v.x), h1 = bf16hi(v.y), h2 = bf16hi(v.z), h3 = bf16hi(v.w);
        *(uint2*)&Ah[(arow0 + 64) * AST + kb] = make_uint2(pack_bf16(h0, h1), pack_bf16(h2, h3));
        *(uint2*)&Al[(arow0 + 64) * AST + kb] = make_uint2(pack_bf16(v.x - h0, v.y - h1),
                                                           pack_bf16(v.z - h2, v.w - h3));
    }
}

// GEMM stage with A from gmem (double-buffered A+B rings). Accumulates into acc.
__device__ __forceinline__ void stage_gmemA(
    const float* __restrict__ A, int lda, int brow, int ktiles,
    const float* __restrict__ B, int ldb, int bc,
    unsigned* AsH, unsigned* AsL, unsigned* BsH, unsigned* BsL,
    float acc[4][4][4], int tid)
{
    float4 ra0, ra1, rb0, rb1;
    a_fetch(A, lda, brow, 0, tid, ra0, ra1);
    b_fetch(B, ldb, 0, bc, tid, rb0, rb1);
    a_stage(AsH, AsL, tid, ra0, ra1);
    b_stage(BsH, BsL, tid, rb0, rb1);
    __syncthreads();
    for (int t = 0; t < ktiles; t++) {
        if (t + 1 < ktiles) {
            a_fetch(A, lda, brow, (t + 1) * 16, tid, ra0, ra1);
            b_fetch(B, ldb, (t + 1) * 16, bc, tid, rb0, rb1);
        }
        const int cur = t & 1;
        mma_chunk(AsH + cur * ABUF, AsL + cur * ABUF, AST, 0,
                  BsH + cur * BBUF, BsL + cur * BBUF, acc, tid);
        if (t + 1 < ktiles) {
            const int nxt = cur ^ 1;
            a_stage(AsH + nxt * ABUF, AsL + nxt * ABUF, tid, ra0, ra1);
            b_stage(BsH + nxt * BBUF, BsL + nxt * BBUF, tid, rb0, rb1);
            __syncthreads();
        }
    }
    __syncthreads();
}

// GEMM stage with A resident in smem intermediate (only B ring). Accumulates.
__device__ __forceinline__ void stage_interA(
    const unsigned* __restrict__ Ih, const unsigned* __restrict__ Il, int ist, int ktiles,
    const float* __restrict__ B, int ldb, int bc,
    unsigned* BsH, unsigned* BsL,
    float acc[4][4][4], int tid)
{
    float4 rb0, rb1;
    b_fetch(B, ldb, 0, bc, tid, rb0, rb1);
    b_stage(BsH, BsL, tid, rb0, rb1);
    __syncthreads();
    for (int t = 0; t < ktiles; t++) {
        if (t + 1 < ktiles) b_fetch(B, ldb, (t + 1) * 16, bc, tid, rb0, rb1);
        const int cur = t & 1;
        mma_chunk(Ih, Il, ist, t * 8, BsH + cur * BBUF, BsL + cur * BBUF, acc, tid);
        if (t + 1 < ktiles) {
            const int nxt = cur ^ 1;
            b_stage(BsH + nxt * BBUF, BsL + nxt * BBUF, tid, rb0, rb1);
            __syncthreads();
        }
    }
    __syncthreads();
}

// epilogue: relu(acc + bias) -> smem intermediate (hi/lo bf16 pairs)
__device__ __forceinline__ void epi_inter(
    float acc[4][4][4], unsigned* Ih, unsigned* Il, int ist, int pair0,
    const float* __restrict__ bias, int tid)
{
    const int lane = tid & 31, w = tid >> 5, gid = lane >> 2, tig = lane & 3;
    const int wm = (w & 1) * 64, wn = (w >> 1) * 32;
#pragma unroll
    for (int ms = 0; ms < 4; ms++) {
        const int r0 = wm + ms * 16 + gid, r1 = r0 + 8;
#pragma unroll
        for (int ns = 0; ns < 4; ns++) {
            const int c = wn + ns * 8 + tig * 2;
            const float b0 = bias[c], b1 = bias[c + 1];
            const float v0 = fmaxf(acc[ms][ns][0] + b0, 0.f);
            const float v1 = fmaxf(acc[ms][ns][1] + b1, 0.f);
            const float v2 = fmaxf(acc[ms][ns][2] + b0, 0.f);
            const float v3 = fmaxf(acc[ms][ns][3] + b1, 0.f);
            const int kp = pair0 + (c >> 1);
            const float h0 = bf16hi(v0), h1 = bf16hi(v1), h2 = bf16hi(v2), h3 = bf16hi(v3);
            Ih[r0 * ist + kp] = pack_bf16(h0, h1);
            Il[r0 * ist + kp] = pack_bf16(v0 - h0, v1 - h1);
            Ih[r1 * ist + kp] = pack_bf16(h2, h3);
            Il[r1 * ist + kp] = pack_bf16(v2 - h2, v3 - h3);
        }
    }
}

// epilogue: acc + bias -> gmem (no relu)
__device__ __forceinline__ void epi_gmem_bias(
    float acc[4][4][4], float* __restrict__ C, int N, int brow, int bcol,
    const float* __restrict__ bias, int tid)
{
    const int lane = tid & 31, w = tid >> 5, gid = lane >> 2, tig = lane & 3;
    const int wm = (w & 1) * 64, wn = (w >> 1) * 32;
#pragma unroll
    for (int ms = 0; ms < 4; ms++) {
        const int r0 = brow + wm + ms * 16 + gid, r1 = r0 + 8;
#pragma unroll
        for (int ns = 0; ns < 4; ns++) {
            const int c = wn + ns * 8 + tig * 2;
            const float b0 = bias[c], b1 = bias[c + 1];
            *(float2*)&C[(size_t)r0 * N + bcol + c] =
                make_float2(acc[ms][ns][0] + b0, acc[ms][ns][1] + b1);
            *(float2*)&C[(size_t)r1 * N + bcol + c] =
                make_float2(acc[ms][ns][2] + b0, acc[ms][ns][3] + b1);
        }
    }
}

// epilogue: raw acc -> fp32 smem tile (stride sstride)
__device__ __forceinline__ void epi_smem(
    float acc[4][4][4], float* __restrict__ S, int sstride, int col0, int tid)
{
    const int lane = tid & 31, w = tid >> 5, gid = lane >> 2, tig = lane & 3;
    const int wm = (w & 1) * 64, wn = (w >> 1) * 32;
#pragma unroll
    for (int ms = 0; ms < 4; ms++) {
        const int r0 = wm + ms * 16 + gid, r1 = r0 + 8;
#pragma unroll
        for (int ns = 0; ns < 4; ns++) {
            const int c = col0 + wn + ns * 8 + tig * 2;
            *(float2*)&S[r0 * sstride + c] = make_float2(acc[ms][ns][0], acc[ms][ns][1]);
            *(float2*)&S[r1 * sstride + c] = make_float2(acc[ms][ns][2], acc[ms][ns][3]);
        }
    }
}

// epilogue: e = (Ein + relu(acc + bias)) * alive  -> gmem (in place over e)
__device__ __forceinline__ void epi_resid(
    float acc[4][4][4], float* __restrict__ Cout, const float* __restrict__ Ein,
    const unsigned char* __restrict__ dones, const float* __restrict__ bias,
    int brow, int tid)
{
    const int lane = tid & 31, w = tid >> 5, gid = lane >> 2, tig = lane & 3;
    const int wm = (w & 1) * 64, wn = (w >> 1) * 32;
#pragma unroll
    for (int ms = 0; ms < 4; ms++) {
        const int r0 = brow + wm + ms * 16 + gid, r1 = r0 + 8;
        const float alive0 = dones[r0] ? 0.f : 1.f;
        const float alive1 = dones[r1] ? 0.f : 1.f;
        const float* E0 = Ein + (size_t)r0 * D;
        const float* E1 = Ein + (size_t)r1 * D;
#pragma unroll
        for (int ns = 0; ns < 4; ns++) {
            const int c = wn + ns * 8 + tig * 2;
            const float b0 = bias[c], b1 = bias[c + 1];
            float v0 = fmaxf(acc[ms][ns][0] + b0, 0.f);
            float v1 = fmaxf(acc[ms][ns][1] + b1, 0.f);
            float v2 = fmaxf(acc[ms][ns][2] + b0, 0.f);
            float v3 = fmaxf(acc[ms][ns][3] + b1, 0.f);
            v0 = (E0[c] + v0) * alive0;   v1 = (E0[c + 1] + v1) * alive0;
            v2 = (E1[c] + v2) * alive1;   v3 = (E1[c + 1] + v3) * alive1;
            *(float2*)&Cout[(size_t)r0 * D + c] = make_float2(v0, v1);
            *(float2*)&Cout[(size_t)r1 * D + c] = make_float2(v2, v3);
        }
    }
}

// epilogue: partial vout dot into smem row-reduction
__device__ __forceinline__ void epi_value(
    float acc[4][4][4], float* __restrict__ sred,
    const float* __restrict__ v2b, const float* __restrict__ vow, int col0, int tid)
{
    const int lane = tid & 31, w = tid >> 5, gid = lane >> 2, tig = lane & 3;
    const int wm = (w & 1) * 64, wn = (w >> 1) * 32;
#pragma unroll
    for (int ms = 0; ms < 4; ms++) {
        const int r0 = wm + ms * 16 + gid, r1 = r0 + 8;
        float p0 = 0.f, p1 = 0.f;
#pragma unroll
        for (int ns = 0; ns < 4; ns++) {
            const int c = col0 + wn + ns * 8 + tig * 2;
            const float b0 = v2b[c], b1 = v2b[c + 1];
            const float w0 = vow[c], w1 = vow[c + 1];
            p0 += fmaxf(acc[ms][ns][0] + b0, 0.f) * w0 + fmaxf(acc[ms][ns][1] + b1, 0.f) * w1;
            p1 += fmaxf(acc[ms][ns][2] + b0, 0.f) * w0 + fmaxf(acc[ms][ns][3] + b1, 0.f) * w1;
        }
        atomicAdd(&sred[r0], p0);
        atomicAdd(&sred[r1], p1);
    }
}

// ================= fused kernels ================================================

// obs -> emb1 -> emb2 -> gi   (one block = 128 rows)
// smem u32 layout: emb1H 0 | emb1L 8704 | emb2H 17408 | emb2L 26112 | BsH 34816(2176) | BsL 36992(2176)
// As ring (stage1 only) overlays emb2 region.
#define SMEM_EMB (39168 * 4)
__global__ __launch_bounds__(256) void fused_embed_kernel(
    const float* __restrict__ obs,
    const float* __restrict__ e1w, const float* __restrict__ e1b,
    const float* __restrict__ e2w, const float* __restrict__ e2b,
    const float* __restrict__ gWi, const float* __restrict__ gbi,
    float* __restrict__ gi)
{
    extern __shared__ unsigned smu[];
    unsigned* emb1H = smu;
    unsigned* emb1L = smu + 8704;
    unsigned* emb2H = smu + 17408;
    unsigned* emb2L = smu + 26112;
    unsigned* BsH   = smu + 34816;
    unsigned* BsL   = smu + 36992;
    unsigned* AsH   = emb2H;          // overlay, dead after stage1
    unsigned* AsL   = emb2H + 2 * ABUF;

    const int tid  = threadIdx.x;
    const int brow = blockIdx.x * 128;
    float acc[4][4][4];

    // stage1: emb1 = relu(obs @ e1w + e1b)   (K=64)
    ZERO_ACC(acc);
    stage_gmemA(obs, OBS, brow, OBS / 16, e1w, D, 0, AsH, AsL, BsH, BsL, acc, tid);
    epi_inter(acc, emb1H, emb1L, IST, 0, e1b, tid);
    __syncthreads();

    // stage2: emb2 = relu(emb1 @ e2w + e2b)
    ZERO_ACC(acc);
    stage_interA(emb1H, emb1L, IST, 8, e2w, D, 0, BsH, BsL, acc, tid);
    epi_inter(acc, emb2H, emb2L, IST, 0, e2b, tid);
    __syncthreads();

    // stage3: gi = emb2 @ gWi + gbi  (3 x 128-col chunks)
    for (int nc = 0; nc < 3; nc++) {
        ZERO_ACC(acc);
        stage_interA(emb2H, emb2L, IST, 8, gWi, 3 * D, nc * 128, BsH, BsL, acc, tid);
        epi_gmem_bias(acc, gi, 3 * D, brow, nc * 128, gbi + nc * 128, tid);
    }
}

// aiaj (in smem) -> coupling -> ctx
// smem u32: SA 0(33280 f32, stride 260) | AsH 33280(3072) | AsL 36352 | BsH 39424(2176) | BsL 41600
//           scw 43776(128) | scb 43904(128) | sC 44032(1024)     SE overlays SA (stride 132)
#define SMEM_CPL (45056 * 4)
__global__ __launch_bounds__(256) void fused_couple_kernel(
    const float* __restrict__ e, const float* __restrict__ chw,
    const float* __restrict__ chb, const float* __restrict__ cow,
    const float* __restrict__ cob, float* __restrict__ ctx)
{
    extern __shared__ unsigned smu[];
    float*    SA  = (float*)smu;
    unsigned* AsH = smu + 33280;
    unsigned* AsL = smu + 36352;
    unsigned* BsH = smu + 39424;
    unsigned* BsL = smu + 41600;
    float*    scw = (float*)(smu + 43776);
    float*    scb = (float*)(smu + 43904);
    float*    sC  = (float*)(smu + 44032);

    const int tid  = threadIdx.x;
    const int brow = blockIdx.x * 128;
    float acc[4][4][4];

    // [ai | aj] = e @ [W1 | W2]  into SA
    for (int nc = 0; nc < 2; nc++) {
        ZERO_ACC(acc);
        stage_gmemA(e, D, brow, 8, chw + (size_t)nc * D * CH, CH, 0,
                    AsH, AsL, BsH, BsL, acc, tid);
        epi_smem(acc, SA, 260, nc * 128, tid);
    }
    if (tid < 128) { scw[tid] = cow[tid]; scb[tid] = chb[tid]; }
    __syncthreads();

    // coupling matrix per 8-row group: sC[g][i*8+j] = (i!=j) * sigmoid(dot + cob)
    const int w = tid >> 5, lane = tid & 31;
    const float cb = cob[0];
    for (int gl = w; gl < 16; gl += 8) {
        for (int ij = 0; ij < 64; ij++) {
            const int i = ij >> 3, j = ij & 7;
            const float* ap = SA + (gl * 8 + i) * 260;
            const float* bp = SA + (gl * 8 + j) * 260 + 128;
            float s = 0.f;
#pragma unroll
            for (int k = lane; k < 128; k += 32) {
                const float v = ap[k] + bp[k] + scb[k];
                s += fmaxf(v, 0.f) * scw[k];
            }
#pragma unroll
            for (int off = 16; off; off >>= 1) s += __shfl_xor_sync(0xffffffffu, s, off);
            if (lane == 0)
                sC[gl * 64 + ij] = (i == j) ? 0.f : 1.f / (1.f + expf(-(s + cb)));
        }
    }
    __syncthreads();

    // load e tile into SE (reuses SA space; e rows are already alive-masked)
    float* SE = SA;
    for (int idx = tid; idx < 128 * 128; idx += 256) {
        const int r = idx >> 7, d = idx & 127;
        SE[r * 132 + d] = e[(size_t)(brow + r) * D + d];
    }
    __syncthreads();

    // ctx = C @ e_group
    for (int idx = tid; idx < 16 * 8 * 128; idx += 256) {
        const int gl = idx >> 10, i = (idx >> 7) & 7, d = idx & 127;
        const float* cp = sC + gl * 64 + i * 8;
        const float* ep = SE + (gl * 8) * 132 + d;
        float s = 0.f;
#pragma unroll
        for (int j = 0; j < 8; j++) s += cp[j] * ep[j * 132];
        ctx[(size_t)(brow + gl * 8 + i) * D + d] = s;
    }
}

// d1 = relu(e@U1 + ctx@U2 + uhb) in smem; e = (e + relu(d1@uow + uob)) * alive
// smem u32: d1H 0(8704) | d1L 8704 | AsH 17408(3072) | AsL 20480 | BsH 23552(2176) | BsL 25728
#define SMEM_UPD (27904 * 4)
__global__ __launch_bounds__(256) void fused_update_kernel(
    const float* __restrict__ e, const float* __restrict__ ctx,
    const float* __restrict__ uhw, const float* __restrict__ uhb,
    const float* __restrict__ uow, const float* __restrict__ uob,
    const unsigned char* __restrict__ dmask, float* __restrict__ e_out)
{
    extern __shared__ unsigned smu[];
    unsigned* d1H = smu;
    unsigned* d1L = smu + 8704;
    unsigned* AsH = smu + 17408;
    unsigned* AsL = smu + 20480;
    unsigned* BsH = smu + 23552;
    unsigned* BsL = smu + 25728;

    const int tid  = threadIdx.x;
    const int brow = blockIdx.x * 128;
    float acc[4][4][4];

    ZERO_ACC(acc);
    stage_gmemA(e,   D, brow, 8, uhw,                 D, 0, AsH, AsL, BsH, BsL, acc, tid);
    stage_gmemA(ctx, D, brow, 8, uhw + (size_t)D * D, D, 0, AsH, AsL, BsH, BsL, acc, tid);
    epi_inter(acc, d1H, d1L, IST, 0, uhb, tid);
    __syncthreads();

    ZERO_ACC(acc);
    stage_interA(d1H, d1L, IST, 8, uow, D, 0, BsH, BsL, acc, tid);
    epi_resid(acc, e_out, e, dmask, uob, brow, tid);
}

// v1 = relu(e@v1w+b) in smem; v2 = relu(v1@v2w+b); values = v2@vow + vob
// smem u32: v1H 0(16896) | v1L 16896 | AsH 33792(3072) | AsL 36864 | BsH 39936(2176) | BsL 42112 | sred 44288(128)
#define SMEM_VAL (44416 * 4)
__global__ __launch_bounds__(256) void fused_value_kernel(
    const float* __restrict__ e,
    const float* __restrict__ v1w, const float* __restrict__ v1b,
    const float* __restrict__ v2w, const float* __restrict__ v2b,
    const float* __restrict__ vow, const float* __restrict__ vob,
    float* __restrict__ out_values)
{
    extern __shared__ unsigned smu[];
    unsigned* v1H = smu;
    unsigned* v1L = smu + 16896;
    unsigned* AsH = smu + 33792;
    unsigned* AsL = smu + 36864;
    unsigned* BsH = smu + 39936;
    unsigned* BsL = smu + 42112;
    float*   sred = (float*)(smu + 44288);

    const int tid  = threadIdx.x;
    const int brow = blockIdx.x * 128;
    float acc[4][4][4];

    // v1 (N=256 in 2 chunks)
    for (int nc = 0; nc < 2; nc++) {
        ZERO_ACC(acc);
        stage_gmemA(e, D, brow, 8, v1w, VH, nc * 128, AsH, AsL, BsH, BsL, acc, tid);
        epi_inter(acc, v1H, v1L, IST2, nc * 64, v1b + nc * 128, tid);
    }
    if (tid < 128) sred[tid] = 0.f;
    __syncthreads();

    // v2 + fused vout reduction (K=256)
    for (int nc = 0; nc < 2; nc++) {
        ZERO_ACC(acc);
        stage_interA(v1H, v1L, IST2, 16, v2w, VH, nc * 128, BsH, BsL, acc, tid);
        epi_value(acc, sred, v2b, vow, nc * 128, tid);
    }
    __syncthreads();
    if (tid < 128) out_values[brow + tid] = sred[tid] + vob[0];
}

// ---------------- persistent GRU scan (unchanged from R10) ---------------------
#define RPB 4
#define GTH 384

__device__ __forceinline__ unsigned long long fma_f32x2(
    unsigned long long a, unsigned long long b, unsigned long long c)
{
    unsigned long long d;
    asm("fma.rn.f32x2 %0, %1, %2, %3;" : "=l"(d) : "l"(a), "l"(b), "l"(c));
    return d;
}

__device__ __forceinline__ float sig_fast(float x)
{
    return __fdividef(1.f, 1.f + __expf(-x));
}
__device__ __forceinline__ float tanh_fast(float x)
{
    return __fdividef(2.f, 1.f + __expf(-2.f * x)) - 1.f;
}

__global__ __launch_bounds__(GTH, 1) void gru_kernel(
    const float* __restrict__ gi,
    const unsigned char* __restrict__ dones,
    const float* __restrict__ h0,
    const float* __restrict__ Wh,
    const float* __restrict__ bhn,
    float* __restrict__ e_out,
    float* __restrict__ hidden_out)
{
    __shared__ __align__(16) float hs2[64 * 8];
    __shared__ float ghs[RPB * 384];
    __shared__ float sbhn[D];

    const int tid = threadIdx.x;
    const int rowbase = blockIdx.x * RPB;

    unsigned long long w[64];
#pragma unroll
    for (int kp = 0; kp < 64; kp++) {
        const unsigned lo = __float_as_uint(Wh[(size_t)(2 * kp) * 384 + tid]);
        const unsigned hi = __float_as_uint(Wh[(size_t)(2 * kp + 1) * 384 + tid]);
        w[kp] = ((unsigned long long)hi << 32) | lo;
    }
    if (tid < D) sbhn[tid] = bhn[tid];

    const int rA = tid >> 7, dA = tid & 127;
    const int rowA = rowbase + rA;
    const bool hasB = (tid < 128);
    const int rowB = rowbase + 3;

    float pa0, pa1, pa2, pb0 = 0.f, pb1 = 0.f, pb2 = 0.f;
    auto prefetch = [&](int t) {
        const size_t gibA = ((size_t)t * BATCH + rowA) * (3 * D);
        pa0 = gi[gibA + dA];
        pa1 = gi[gibA + D + dA];
        pa2 = gi[gibA + 2 * D + dA];
        if (hasB) {
            const size_t gibB = ((size_t)t * BATCH + rowB) * (3 * D);
            pb0 = gi[gibB + tid];
            pb1 = gi[gibB + D + tid];
            pb2 = gi[gibB + 2 * D + tid];
        }
    };

    for (int idx = tid; idx < RPB * D; idx += GTH) {
        const int r = idx >> 7, d = idx & 127;
        const int row = rowbase + r;
        float v = dones[row] ? 0.f : h0[(size_t)row * D + d];
        hs2[(d >> 1) * 8 + r * 2 + (d & 1)] = v;
    }
    prefetch(0);
    __syncthreads();

    for (int t = 0; t < T_STEPS; t++) {
        {
            unsigned long long a0 = 0, a1 = 0, a2 = 0, a3 = 0;
#pragma unroll
            for (int kp = 0; kp < 64; kp++) {
                const ulonglong2 p01 = *(const ulonglong2*)(hs2 + kp * 8);
                const ulonglong2 p23 = *(const ulonglong2*)(hs2 + kp * 8 + 4);
                a0 = fma_f32x2(w[kp], p01.x, a0);
                a1 = fma_f32x2(w[kp], p01.y, a1);
                a2 = fma_f32x2(w[kp], p23.x, a2);
                a3 = fma_f32x2(w[kp], p23.y, a3);
            }
            ghs[0 * 384 + tid] = __uint_as_float((unsigned)a0) + __uint_as_float((unsigned)(a0 >> 32));
            ghs[1 * 384 + tid] = __uint_as_float((unsigned)a1) + __uint_as_float((unsigned)(a1 >> 32));
            ghs[2 * 384 + tid] = __uint_as_float((unsigned)a2) + __uint_as_float((unsigned)(a2 >> 32));
            ghs[3 * 384 + tid] = __uint_as_float((unsigned)a3) + __uint_as_float((unsigned)(a3 >> 32));
        }
        __syncthreads();

        {
            {
                const int r = rA, d = dA, row = rowA;
                const float h_r = ghs[r * 384 + d];
                const float h_z = ghs[r * 384 + D + d];
                const float h_n = ghs[r * 384 + 2 * D + d];
                const int hsidx = (d >> 1) * 8 + r * 2 + (d & 1);
                const float hprev = hs2[hsidx];
                const float rg = sig_fast(pa0 + h_r);
                const float zg = sig_fast(pa1 + h_z);
                const float ng = tanh_fast(pa2 + rg * (h_n + sbhn[d]));
                const float hn = (1.f - zg) * ng + zg * hprev;
                const float alive = dones[t * BATCH + row] ? 0.f : 1.f;
                e_out[((size_t)t * BATCH + row) * D + d] = hn * alive;
                if (t == T_STEPS - 1) hidden_out[(size_t)row * D + d] = hn;
                else hs2[hsidx] = dones[(t + 1) * BATCH + row] ? 0.f : hn;
            }
            if (hasB) {
                const int r = 3, d = tid, row = rowB;
                const float h_r = ghs[r * 384 + d];
                const float h_z = ghs[r * 384 + D + d];
                const float h_n = ghs[r * 384 + 2 * D + d];
                const int hsidx = (d >> 1) * 8 + r * 2 + (d & 1);
                const float hprev = hs2[hsidx];
                const float rg = sig_fast(pb0 + h_r);
                const float zg = sig_fast(pb1 + h_z);
                const float ng = tanh_fast(pb2 + rg * (h_n + sbhn[d]));
                const float hn = (1.f - zg) * ng + zg * hprev;
                const float alive = dones[t * BATCH + row] ? 0.f : 1.f;
                e_out[((size_t)t * BATCH + row) * D + d] = hn * alive;
                if (t == T_STEPS - 1) hidden_out[(size_t)row * D + d] = hn;
                else hs2[hsidx] = dones[(t + 1) * BATCH + row] ? 0.f : hn;
            }
        }
        if (t + 1 < T_STEPS) prefetch(t + 1);
        __syncthreads();
    }
}

// ---------------- launcher -------------------------------------------------------
extern "C" void kernel_launch(void* const* d_in, const int* in_sizes, int n_in,
                              void* d_out, int out_size)
{
    const float* hidden = (const float*)d_in[0];
    const float* obs    = (const float*)d_in[1];
    const void*  dones_raw = d_in[2];
    const float* e1w = (const float*)d_in[3];
    const float* e1b = (const float*)d_in[4];
    const float* e2w = (const float*)d_in[5];
    const float* e2b = (const float*)d_in[6];
    const float* gWi = (const float*)d_in[7];
    const float* gbi = (const float*)d_in[8];
    const float* gWh = (const float*)d_in[9];
    const float* gbhn = (const float*)d_in[10];
    const float* chw = (const float*)d_in[11];
    const float* chb = (const float*)d_in[12];
    const float* cow = (const float*)d_in[13];
    const float* cob = (const float*)d_in[14];
    const float* uhw = (const float*)d_in[15];
    const float* uhb = (const float*)d_in[16];
    const float* uow = (const float*)d_in[17];
    const float* uob = (const float*)d_in[18];
    const float* v1w = (const float*)d_in[19];
    const float* v1b = (const float*)d_in[20];
    const float* v2w = (const float*)d_in[21];
    const float* v2b = (const float*)d_in[22];
    const float* vow = (const float*)d_in[23];
    const float* vob = (const float*)d_in[24];

    float* out_hidden = (float*)d_out;                 // (B, D)
    float* out_values = (float*)d_out + BATCH * D;     // (T, B)

    float *gi, *e, *ctx;
    unsigned char* dmask;
    cudaGetSymbolAddress((void**)&gi,   g_gi);
    cudaGetSymbolAddress((void**)&e,    g_e);
    cudaGetSymbolAddress((void**)&ctx,  g_ctx);
    cudaGetSymbolAddress((void**)&dmask, g_dmask);

    cudaFuncSetAttribute(fused_embed_kernel,  cudaFuncAttributeMaxDynamicSharedMemorySize, SMEM_EMB);
    cudaFuncSetAttribute(fused_couple_kernel, cudaFuncAttributeMaxDynamicSharedMemorySize, SMEM_CPL);
    cudaFuncSetAttribute(fused_update_kernel, cudaFuncAttributeMaxDynamicSharedMemorySize, SMEM_UPD);
    cudaFuncSetAttribute(fused_value_kernel,  cudaFuncAttributeMaxDynamicSharedMemorySize, SMEM_VAL);

    detect_dones_kernel<<<1, 256>>>((const unsigned char*)dones_raw, TB);
    conv_dones_kernel<<<TB / 256, 256>>>(dones_raw, TB);

    fused_embed_kernel<<<TB / 128, 256, SMEM_EMB>>>(obs, e1w, e1b, e2w, e2b, gWi, gbi, gi);

    gru_kernel<<<BATCH / RPB, GTH>>>(gi, dmask, hidden, gWh, gbhn, e, out_hidden);

    for (int it = 0; it < ITERS; it++) {
        fused_couple_kernel<<<TB / 128, 256, SMEM_CPL>>>(e, chw, chb, cow, cob, ctx);
        fused_update_kernel<<<TB / 128, 256, SMEM_UPD>>>(e, ctx, uhw, uhb, uow, uob, dmask, e);
    }

    fused_value_kernel<<<TB / 128, 256, SMEM_VAL>>>(e, v1w, v1b, v2w, v2b, vow, vob, out_values);
}

// round 12
// speedup vs baseline: 1.2431x; 1.2431x over previous
#include <cuda_runtime.h>
#include <cuda_bf16.h>
#include <math.h>

#define T_STEPS 128
#define NE 64
#define NA 8
#define OBS 64
#define D 128
#define CH 128
#define VH 256
#define BATCH 512           // NE*NA
#define TB (T_STEPS*BATCH)  // 65536
#define ITERS 2

// ---------------- scratch (static device arrays: allocation-free) -------------
__device__ float g_emb1[TB * D];
__device__ float g_emb2[TB * D];
__device__ float g_gi[TB * 3 * D];
__device__ float g_e[TB * D];
__device__ float g_aiaj[TB * 2 * CH];   // merged [ai | aj], row stride 256
__device__ float g_ctx[TB * D];
__device__ float g_d1[TB * D];
__device__ float g_v1[TB * VH];
__device__ float g_v2[TB * VH];
__device__ unsigned char g_dmask[TB];
__device__ int g_dflag;   // 0 = uint8/bool, 1 = float32, 2 = int32

// ---------------- dones dtype detection + canonicalization --------------------
__global__ void detect_dones_kernel(const unsigned char* __restrict__ p, int n)
{
    __shared__ int s_nonbin, s_off4;
    if (threadIdx.x == 0) { s_nonbin = 0; s_off4 = 0; }
    __syncthreads();
    int nb = 0, o4 = 0;
    for (int i = threadIdx.x; i < n; i += blockDim.x) {
        const unsigned char b = p[i];
        if (b > 1) nb = 1;
        else if (b == 1 && (i & 3)) o4 = 1;
    }
    if (nb) atomicOr(&s_nonbin, 1);
    if (o4) atomicOr(&s_off4, 1);
    __syncthreads();
    if (threadIdx.x == 0)
        g_dflag = s_nonbin ? 1 : (s_off4 ? 0 : 2);
}

__global__ void conv_dones_kernel(const void* __restrict__ p, int n)
{
    const int i = blockIdx.x * blockDim.x + threadIdx.x;
    if (i >= n) return;
    const int f = g_dflag;
    unsigned char m;
    if (f == 1)      m = (((const float*)p)[i] != 0.f);
    else if (f == 2) m = (((const int*)p)[i] != 0);
    else             m = (((const unsigned char*)p)[i] != 0);
    g_dmask[i] = m;
}

// ---------------- BF16 tensor-core GEMM (2-way split, 3 products ~ fp32) -------
// C[M,N] = epilogue( A[M,K] @ B[K,N] (+ A2 @ B2) + bias )
// flags: 1 relu | 2 dual-source | 4 resid+alive | 8 B column-split
#define BM 128
#define BN 128
#define BK 16
#define AST 12      // As row stride in u32
#define BST 136     // Bs row stride in u32

__device__ __forceinline__ unsigned pack_bf16(float lo_elem, float hi_elem)
{
    unsigned d;
    asm("cvt.rn.bf16x2.f32 %0, %1, %2;" : "=r"(d) : "f"(hi_elem), "f"(lo_elem));
    return d;
}

__device__ __forceinline__ void mma_bf16(float* c, const unsigned* a, const unsigned* b)
{
    asm volatile(
        "mma.sync.aligned.m16n8k16.row.col.f32.bf16.bf16.f32 "
        "{%0,%1,%2,%3}, {%4,%5,%6,%7}, {%8,%9}, {%0,%1,%2,%3};"
        : "+f"(c[0]), "+f"(c[1]), "+f"(c[2]), "+f"(c[3])
        : "r"(a[0]), "r"(a[1]), "r"(a[2]), "r"(a[3]), "r"(b[0]), "r"(b[1]));
}

__device__ __forceinline__ void ldsm_x4(unsigned& r0, unsigned& r1, unsigned& r2,
                                        unsigned& r3, unsigned addr)
{
    asm volatile("ldmatrix.sync.aligned.m8n8.x4.shared.b16 {%0,%1,%2,%3}, [%4];"
                 : "=r"(r0), "=r"(r1), "=r"(r2), "=r"(r3) : "r"(addr));
}

__global__ __launch_bounds__(256) void tgemm_kernel(
    int M, int N, int K, int ldb,
    const float* __restrict__ A, const float* __restrict__ Bm,
    const float* __restrict__ A2, const float* __restrict__ B2,
    const float* __restrict__ bias, float* __restrict__ Cout,
    int flags, const float* __restrict__ Ein,
    const unsigned char* __restrict__ dones)
{
    __shared__ __align__(16) unsigned As[2][2][BM * AST];       // [buf][hi/lo]
    __shared__ __align__(16) unsigned Bs[2][2][(BK / 2) * BST];

    const int tid  = threadIdx.x;
    const int brow = blockIdx.y * BM;
    const int bcol = blockIdx.x * BN;
    const int w    = tid >> 5, lane = tid & 31;
    const int gid  = lane >> 2, tig = lane & 3;
    const int wm   = (w & 1) * 64;
    const int wn   = (w >> 1) * 32;

    const int arow0 = tid >> 2;
    const int brw   = tid >> 5;
    const int bfc   = (tid & 31) * 4;

    // ldmatrix per-lane address precompute: tile rows = wm+ms*16+(lane&15),
    // u32 col = ((lane&16)>>2) (kpairs 0-3 / 4-7)
    const unsigned aSmemBase = (unsigned)__cvta_generic_to_shared(&As[0][0][0]);
    const unsigned laneOff = ((wm + (lane & 15)) * AST + ((lane & 16) >> 2)) * 4;

    float acc[4][4][4];
#pragma unroll
    for (int i = 0; i < 4; i++)
#pragma unroll
        for (int j = 0; j < 4; j++)
#pragma unroll
            for (int q = 0; q < 4; q++) acc[i][j][q] = 0.f;

    const int nsrc = (flags & 2) ? 2 : 1;
    const int tilesPerSrc = K / BK;
    const int ntiles = nsrc * tilesPerSrc;

    float4 rA[2], rB[2];

    auto loadTile = [&](int t) {
        const int s  = (t >= tilesPerSrc) ? 1 : 0;
        const int k0 = (t - s * tilesPerSrc) * BK;
        const float* Ap = s ? A2 : A;
        const float* Bp;
        int bc;
        if (flags & 8) { Bp = (bcol >= BN) ? B2 : Bm; bc = 0; }
        else           { Bp = s ? B2 : Bm;            bc = bcol; }
        const int afc = (tid & 3) * 4;
        rA[0] = *(const float4*)(Ap + (size_t)(brow + arow0) * K + k0 + afc);
        rA[1] = *(const float4*)(Ap + (size_t)(brow + arow0 + 64) * K + k0 + afc);
        rB[0] = *(const float4*)(Bp + (size_t)(k0 + 2 * brw) * ldb + bc + bfc);
        rB[1] = *(const float4*)(Bp + (size_t)(k0 + 2 * brw + 1) * ldb + bc + bfc);
    };

    auto storeTile = [&](int buf) {
#pragma unroll
        for (int p = 0; p < 2; p++) {
            const float4 v = rA[p];
            const float h0 = __bfloat162float(__float2bfloat16(v.x));
            const float h1 = __bfloat162float(__float2bfloat16(v.y));
            const float h2 = __bfloat162float(__float2bfloat16(v.z));
            const float h3 = __bfloat162float(__float2bfloat16(v.w));
            const int base = (arow0 + p * 64) * AST + (tid & 3) * 2;
            *(uint2*)&As[buf][0][base] = make_uint2(pack_bf16(h0, h1), pack_bf16(h2, h3));
            *(uint2*)&As[buf][1][base] = make_uint2(pack_bf16(v.x - h0, v.y - h1),
                                                    pack_bf16(v.z - h2, v.w - h3));
        }
        {
            const float4 va = rB[0], vb = rB[1];
            const float ha0 = __bfloat162float(__float2bfloat16(va.x));
            const float ha1 = __bfloat162float(__float2bfloat16(va.y));
            const float ha2 = __bfloat162float(__float2bfloat16(va.z));
            const float ha3 = __bfloat162float(__float2bfloat16(va.w));
            const float hb0 = __bfloat162float(__float2bfloat16(vb.x));
            const float hb1 = __bfloat162float(__float2bfloat16(vb.y));
            const float hb2 = __bfloat162float(__float2bfloat16(vb.z));
            const float hb3 = __bfloat162float(__float2bfloat16(vb.w));
            const int base = brw * BST + bfc;
            *(uint4*)&Bs[buf][0][base] = make_uint4(
                pack_bf16(ha0, hb0), pack_bf16(ha1, hb1),
                pack_bf16(ha2, hb2), pack_bf16(ha3, hb3));
            *(uint4*)&Bs[buf][1][base] = make_uint4(
                pack_bf16(va.x - ha0, vb.x - hb0), pack_bf16(va.y - ha1, vb.y - hb1),
                pack_bf16(va.z - ha2, vb.z - hb2), pack_bf16(va.w - ha3, vb.w - hb3));
        }
    };

    loadTile(0);
    storeTile(0);
    __syncthreads();

    for (int t = 0; t < ntiles; t++) {
        if (t + 1 < ntiles) loadTile(t + 1);

        const int cur = t & 1;
        const unsigned* Bsh = Bs[cur][0];
        const unsigned* Bsl = Bs[cur][1];
        const unsigned aTileH = aSmemBase + (unsigned)(cur * (2 * BM * AST * 4)) + laneOff;
        const unsigned aTileL = aTileH + (unsigned)(BM * AST * 4);

        unsigned bh[4][2], bl[4][2];
#pragma unroll
        for (int ns = 0; ns < 4; ns++) {
            const int n = wn + ns * 8 + gid;
            bh[ns][0] = Bsh[tig * BST + n];
            bh[ns][1] = Bsh[(tig + 4) * BST + n];
            bl[ns][0] = Bsl[tig * BST + n];
            bl[ns][1] = Bsl[(tig + 4) * BST + n];
        }
#pragma unroll
        for (int ms = 0; ms < 4; ms++) {
            unsigned ah[4], al[4];
            ldsm_x4(ah[0], ah[1], ah[2], ah[3], aTileH + (unsigned)(ms * 16 * AST * 4));
            ldsm_x4(al[0], al[1], al[2], al[3], aTileL + (unsigned)(ms * 16 * AST * 4));
#pragma unroll
            for (int ns = 0; ns < 4; ns++) {
                mma_bf16(acc[ms][ns], ah, bh[ns]);
                mma_bf16(acc[ms][ns], ah, bl[ns]);
                mma_bf16(acc[ms][ns], al, bh[ns]);
            }
        }

        if (t + 1 < ntiles) {
            storeTile((t + 1) & 1);
            __syncthreads();
        }
    }

    const bool hasb   = (bias != nullptr);
    const bool resid  = (flags & 4);
    const bool dorelu = (flags & 5);
#pragma unroll
    for (int ms = 0; ms < 4; ms++) {
        const int r0 = brow + wm + ms * 16 + gid;
        const int r1 = r0 + 8;
        float alive0 = 1.f, alive1 = 1.f;
        const float *E0 = nullptr, *E1 = nullptr;
        if (resid) {
            alive0 = dones[r0] ? 0.f : 1.f;
            alive1 = dones[r1] ? 0.f : 1.f;
            E0 = Ein + (size_t)r0 * N;
            E1 = Ein + (size_t)r1 * N;
        }
#pragma unroll
        for (int ns = 0; ns < 4; ns++) {
            const int c = bcol + wn + ns * 8 + tig * 2;
            float b0 = 0.f, b1 = 0.f;
            if (hasb) { b0 = bias[c]; b1 = bias[c + 1]; }
            float v0 = acc[ms][ns][0] + b0;
            float v1 = acc[ms][ns][1] + b1;
            float v2 = acc[ms][ns][2] + b0;
            float v3 = acc[ms][ns][3] + b1;
            if (dorelu) {
                v0 = fmaxf(v0, 0.f); v1 = fmaxf(v1, 0.f);
                v2 = fmaxf(v2, 0.f); v3 = fmaxf(v3, 0.f);
            }
            if (resid) {
                v0 = (E0[c] + v0) * alive0;     v1 = (E0[c + 1] + v1) * alive0;
                v2 = (E1[c] + v2) * alive1;     v3 = (E1[c + 1] + v3) * alive1;
            }
            *(float2*)&Cout[(size_t)r0 * N + c] = make_float2(v0, v1);
            *(float2*)&Cout[(size_t)r1 * N + c] = make_float2(v2, v3);
        }
    }
}

// ---------------- persistent GRU scan: Wh in registers, f32x2 FMA, gi prefetch -
#define RPB 4
#define GTH 384

__device__ __forceinline__ unsigned long long fma_f32x2(
    unsigned long long a, unsigned long long b, unsigned long long c)
{
    unsigned long long d;
    asm("fma.rn.f32x2 %0, %1, %2, %3;" : "=l"(d) : "l"(a), "l"(b), "l"(c));
    return d;
}

__device__ __forceinline__ float sig_fast(float x)
{
    return __fdividef(1.f, 1.f + __expf(-x));
}
__device__ __forceinline__ float tanh_fast(float x)
{
    return __fdividef(2.f, 1.f + __expf(-2.f * x)) - 1.f;
}

__global__ __launch_bounds__(GTH, 1) void gru_kernel(
    const float* __restrict__ gi,
    const unsigned char* __restrict__ dones,
    const float* __restrict__ h0,
    const float* __restrict__ Wh,
    const float* __restrict__ bhn,
    float* __restrict__ e_out,
    float* __restrict__ hidden_out)
{
    __shared__ __align__(16) float hs2[64 * 8];   // [kpair][r*2 + (lo/hi)]
    __shared__ float ghs[RPB * 384];
    __shared__ float sbhn[D];

    const int tid = threadIdx.x;
    const int rowbase = blockIdx.x * RPB;

    unsigned long long w[64];
#pragma unroll
    for (int kp = 0; kp < 64; kp++) {
        const unsigned lo = __float_as_uint(Wh[(size_t)(2 * kp) * 384 + tid]);
        const unsigned hi = __float_as_uint(Wh[(size_t)(2 * kp + 1) * 384 + tid]);
        w[kp] = ((unsigned long long)hi << 32) | lo;
    }
    if (tid < D) sbhn[tid] = bhn[tid];

    const int rA = tid >> 7, dA = tid & 127;
    const int rowA = rowbase + rA;
    const bool hasB = (tid < 128);
    const int rowB = rowbase + 3;

    float pa0, pa1, pa2, pb0 = 0.f, pb1 = 0.f, pb2 = 0.f;
    auto prefetch = [&](int t) {
        const size_t gibA = ((size_t)t * BATCH + rowA) * (3 * D);
        pa0 = gi[gibA + dA];
        pa1 = gi[gibA + D + dA];
        pa2 = gi[gibA + 2 * D + dA];
        if (hasB) {
            const size_t gibB = ((size_t)t * BATCH + rowB) * (3 * D);
            pb0 = gi[gibB + tid];
            pb1 = gi[gibB + D + tid];
            pb2 = gi[gibB + 2 * D + tid];
        }
    };

    for (int idx = tid; idx < RPB * D; idx += GTH) {
        const int r = idx >> 7, d = idx & 127;
        const int row = rowbase + r;
        float v = dones[row] ? 0.f : h0[(size_t)row * D + d];
        hs2[(d >> 1) * 8 + r * 2 + (d & 1)] = v;
    }
    prefetch(0);
    __syncthreads();

    for (int t = 0; t < T_STEPS; t++) {
        {
            unsigned long long a0 = 0, a1 = 0, a2 = 0, a3 = 0;
#pragma unroll
            for (int kp = 0; kp < 64; kp++) {
                const ulonglong2 p01 = *(const ulonglong2*)(hs2 + kp * 8);
                const ulonglong2 p23 = *(const ulonglong2*)(hs2 + kp * 8 + 4);
                a0 = fma_f32x2(w[kp], p01.x, a0);
                a1 = fma_f32x2(w[kp], p01.y, a1);
                a2 = fma_f32x2(w[kp], p23.x, a2);
                a3 = fma_f32x2(w[kp], p23.y, a3);
            }
            ghs[0 * 384 + tid] = __uint_as_float((unsigned)a0) + __uint_as_float((unsigned)(a0 >> 32));
            ghs[1 * 384 + tid] = __uint_as_float((unsigned)a1) + __uint_as_float((unsigned)(a1 >> 32));
            ghs[2 * 384 + tid] = __uint_as_float((unsigned)a2) + __uint_as_float((unsigned)(a2 >> 32));
            ghs[3 * 384 + tid] = __uint_as_float((unsigned)a3) + __uint_as_float((unsigned)(a3 >> 32));
        }
        __syncthreads();

        {
            {
                const int r = rA, d = dA, row = rowA;
                const float h_r = ghs[r * 384 + d];
                const float h_z = ghs[r * 384 + D + d];
                const float h_n = ghs[r * 384 + 2 * D + d];
                const int hsidx = (d >> 1) * 8 + r * 2 + (d & 1);
                const float hprev = hs2[hsidx];
                const float rg = sig_fast(pa0 + h_r);
                const float zg = sig_fast(pa1 + h_z);
                const float ng = tanh_fast(pa2 + rg * (h_n + sbhn[d]));
                const float hn = (1.f - zg) * ng + zg * hprev;
                const float alive = dones[t * BATCH + row] ? 0.f : 1.f;
                e_out[((size_t)t * BATCH + row) * D + d] = hn * alive;
                if (t == T_STEPS - 1) hidden_out[(size_t)row * D + d] = hn;
                else hs2[hsidx] = dones[(t + 1) * BATCH + row] ? 0.f : hn;
            }
            if (hasB) {
                const int r = 3, d = tid, row = rowB;
                const float h_r = ghs[r * 384 + d];
                const float h_z = ghs[r * 384 + D + d];
                const float h_n = ghs[r * 384 + 2 * D + d];
                const int hsidx = (d >> 1) * 8 + r * 2 + (d & 1);
                const float hprev = hs2[hsidx];
                const float rg = sig_fast(pb0 + h_r);
                const float zg = sig_fast(pb1 + h_z);
                const float ng = tanh_fast(pb2 + rg * (h_n + sbhn[d]));
                const float hn = (1.f - zg) * ng + zg * hprev;
                const float alive = dones[t * BATCH + row] ? 0.f : 1.f;
                e_out[((size_t)t * BATCH + row) * D + d] = hn * alive;
                if (t == T_STEPS - 1) hidden_out[(size_t)row * D + d] = hn;
                else hs2[hsidx] = dones[(t + 1) * BATCH + row] ? 0.f : hn;
            }
        }
        if (t + 1 < T_STEPS) prefetch(t + 1);
        __syncthreads();
    }
}

// ---------------- fused pairwise-coupling C + context (lane-parallel j) --------
// one block per (t, group). C_ij computed with lane = (j, k-slice): 2 shuffles
// instead of 5 serial per j. alive[j] factor dropped: e_j is already zeroed.
__global__ __launch_bounds__(256) void couple_ctx_kernel(
    const float* __restrict__ e, const float* __restrict__ aiaj,
    const float* __restrict__ chb,
    const float* __restrict__ cow, const float* __restrict__ cob,
    float* __restrict__ ctx)
{
    __shared__ float sai[NA * 132];     // [i][k] stride 132
    __shared__ float sajt[128 * 9];     // [k][j] stride 9 (transposed)
    __shared__ float se[NA * D];
    __shared__ float sb[CH], sw[CH];
    __shared__ float sC[NA * NA];

    const int g  = blockIdx.x;          // t*NE + group
    const size_t base  = (size_t)g * NA * D;
    const size_t base2 = (size_t)g * NA * 256;
    const int tid = threadIdx.x;
    const int lane = tid & 31, warp = tid >> 5;

    {
        const int j = warp;             // agent row 0..7
        const int k0 = lane * 4;
        const float4 vi = *(const float4*)&aiaj[base2 + j * 256 + k0];
        const float4 vj = *(const float4*)&aiaj[base2 + j * 256 + 128 + k0];
        *(float4*)&sai[j * 132 + k0] = vi;
        sajt[(k0 + 0) * 9 + j] = vj.x;
        sajt[(k0 + 1) * 9 + j] = vj.y;
        sajt[(k0 + 2) * 9 + j] = vj.z;
        sajt[(k0 + 3) * 9 + j] = vj.w;
    }
    *(float4*)&se[tid * 4] = *(const float4*)&e[base + tid * 4];
    if (tid < CH) { sb[tid] = chb[tid]; sw[tid] = cow[tid]; }
    __syncthreads();

    // coupling: warp = i; lane -> (j = lane&7, slice = lane>>3 of 32 ks)
    {
        const int i = warp;
        const int jj = lane & 7, slice = lane >> 3;
        const float cb = cob[0];
        float s = 0.f;
#pragma unroll
        for (int it = 0; it < 32; it++) {
            const int kk = slice * 32 + ((it + slice * 8) & 31);  // bank-disperse
            const float v = sai[i * 132 + kk] + sajt[kk * 9 + jj] + sb[kk];
            s += fmaxf(v, 0.f) * sw[kk];
        }
        s += __shfl_xor_sync(0xffffffffu, s, 8);
        s += __shfl_xor_sync(0xffffffffu, s, 16);
        if (lane < 8)
            sC[i * NA + lane] = (i == lane) ? 0.f : 1.f / (1.f + expf(-(s + cb)));
    }
    __syncthreads();

    // ctx = C @ e_group
    for (int idx = tid; idx < NA * D; idx += 256) {
        const int i = idx >> 7, d = idx & 127;
        float s = 0.f;
#pragma unroll
        for (int j = 0; j < NA; j++) s += sC[i * NA + j] * se[j * D + d];
        ctx[base + idx] = s;
    }
}

// ---------------- final value projection (VH -> 1) ------------------------------
__global__ __launch_bounds__(256) void vout_kernel(
    const float* __restrict__ v2, const float* __restrict__ w,
    const float* __restrict__ b, float* __restrict__ out)
{
    __shared__ float sw[VH];
    const int tid = threadIdx.x;
    sw[tid] = w[tid];
    __syncthreads();
    const int warp = tid >> 5, lane = tid & 31;
    const int row = blockIdx.x * 8 + warp;
    const float* vp = v2 + (size_t)row * VH;
    float s = 0.f;
#pragma unroll
    for (int k = lane; k < VH; k += 32) s += vp[k] * sw[k];
#pragma unroll
    for (int off = 16; off; off >>= 1) s += __shfl_xor_sync(0xffffffffu, s, off);
    if (lane == 0) out[row] = s + b[0];
}

// ---------------- launcher -------------------------------------------------------
extern "C" void kernel_launch(void* const* d_in, const int* in_sizes, int n_in,
                              void* d_out, int out_size)
{
    const float* hidden = (const float*)d_in[0];
    const float* obs    = (const float*)d_in[1];
    const void*  dones_raw = d_in[2];
    const float* e1w = (const float*)d_in[3];
    const float* e1b = (const float*)d_in[4];
    const float* e2w = (const float*)d_in[5];
    const float* e2b = (const float*)d_in[6];
    const float* gWi = (const float*)d_in[7];
    const float* gbi = (const float*)d_in[8];
    const float* gWh = (const float*)d_in[9];
    const float* gbhn = (const float*)d_in[10];
    const float* chw = (const float*)d_in[11];
    const float* chb = (const float*)d_in[12];
    const float* cow = (const float*)d_in[13];
    const float* cob = (const float*)d_in[14];
    const float* uhw = (const float*)d_in[15];
    const float* uhb = (const float*)d_in[16];
    const float* uow = (const float*)d_in[17];
    const float* uob = (const float*)d_in[18];
    const float* v1w = (const float*)d_in[19];
    const float* v1b = (const float*)d_in[20];
    const float* v2w = (const float*)d_in[21];
    const float* v2b = (const float*)d_in[22];
    const float* vow = (const float*)d_in[23];
    const float* vob = (const float*)d_in[24];

    float* out_hidden = (float*)d_out;                 // (B, D)
    float* out_values = (float*)d_out + BATCH * D;     // (T, B)

    float *emb1, *emb2, *gi, *e, *aiaj, *ctx, *d1, *v1, *v2;
    unsigned char* dmask;
    cudaGetSymbolAddress((void**)&emb1, g_emb1);
    cudaGetSymbolAddress((void**)&emb2, g_emb2);
    cudaGetSymbolAddress((void**)&gi,   g_gi);
    cudaGetSymbolAddress((void**)&e,    g_e);
    cudaGetSymbolAddress((void**)&aiaj, g_aiaj);
    cudaGetSymbolAddress((void**)&ctx,  g_ctx);
    cudaGetSymbolAddress((void**)&d1,   g_d1);
    cudaGetSymbolAddress((void**)&v1,   g_v1);
    cudaGetSymbolAddress((void**)&v2,   g_v2);
    cudaGetSymbolAddress((void**)&dmask, g_dmask);

    const int M = TB;
    const dim3 blk(256);

    detect_dones_kernel<<<1, 256>>>((const unsigned char*)dones_raw, TB);
    conv_dones_kernel<<<TB / 256, 256>>>(dones_raw, TB);

    // embed1: relu(obs @ e1w + e1b)
    tgemm_kernel<<<dim3(D / BN, M / BM), blk>>>(M, D, OBS, D, obs, e1w,
        nullptr, nullptr, e1b, emb1, 1, nullptr, nullptr);
    // embed2: relu(emb1 @ e2w + e2b)
    tgemm_kernel<<<dim3(D / BN, M / BM), blk>>>(M, D, D, D, emb1, e2w,
        nullptr, nullptr, e2b, emb2, 1, nullptr, nullptr);
    // gi = emb2 @ gWi + gbi
    tgemm_kernel<<<dim3(3 * D / BN, M / BM), blk>>>(M, 3 * D, D, 3 * D, emb2, gWi,
        nullptr, nullptr, gbi, gi, 0, nullptr, nullptr);
    // sequential GRU scan
    gru_kernel<<<BATCH / RPB, GTH>>>(gi, dmask, hidden, gWh, gbhn, e, out_hidden);

    for (int it = 0; it < ITERS; it++) {
        // [ai | aj] = e @ [W1 | W2]
        tgemm_kernel<<<dim3(2 * CH / BN, M / BM), blk>>>(M, 2 * CH, D, CH, e, chw,
            nullptr, chw + (size_t)D * CH, nullptr, aiaj, 8, nullptr, nullptr);
        couple_ctx_kernel<<<T_STEPS * NE, 256>>>(e, aiaj, chb, cow, cob, ctx);
        // d1 = relu(e @ U1 + ctx @ U2 + uhb)
        tgemm_kernel<<<dim3(D / BN, M / BM), blk>>>(M, D, D, D, e, uhw,
            ctx, uhw + (size_t)D * D, uhb, d1, 1 | 2, nullptr, nullptr);
        // e = (e + relu(d1 @ uow + uob)) * alive   (in place)
        tgemm_kernel<<<dim3(D / BN, M / BM), blk>>>(M, D, D, D, d1, uow,
            nullptr, nullptr, uob, e, 4, e, dmask);
    }

    // value head
    tgemm_kernel<<<dim3(VH / BN, M / BM), blk>>>(M, VH, D, VH, e, v1w,
        nullptr, nullptr, v1b, v1, 1, nullptr, nullptr);
    tgemm_kernel<<<dim3(VH / BN, M / BM), blk>>>(M, VH, VH, VH, v1, v2w,
        nullptr, nullptr, v2b, v2, 1, nullptr, nullptr);
    vout_kernel<<<TB / 8, 256>>>(v2, vow, vob, out_values);
}

// round 13
// speedup vs baseline: 1.2768x; 1.0271x over previous
#include <cuda_runtime.h>
#include <cuda_bf16.h>
#include <math.h>

#define T_STEPS 128
#define NE 64
#define NA 8
#define OBS 64
#define D 128
#define CH 128
#define VH 256
#define BATCH 512           // NE*NA
#define TB (T_STEPS*BATCH)  // 65536
#define ITERS 2

// ---------------- scratch (static device arrays: allocation-free) -------------
__device__ float g_emb1[TB * D];
__device__ float g_emb2[TB * D];
__device__ float g_gi[TB * 3 * D];
__device__ float g_e[TB * D];
__device__ float g_aiaj[TB * 2 * CH];   // merged [ai | aj], row stride 256
__device__ float g_ctx[TB * D];
__device__ float g_d1[TB * D];
__device__ float g_v1[TB * VH];
__device__ float g_v2[TB * VH];
__device__ unsigned char g_dmask[TB];
__device__ int g_dflag;
__device__ unsigned g_wpk[253952];      // packed bf16 hi/lo weights (u32)

// packed-weight offsets (u32): hi at HOF, lo at HOF+SZ
// e1w  sz 4096  hoff 0
// e2w  sz 8192  hoff 8192
// gWi  sz 24576 hoff 24576
// chw  sz 16384 hoff 73728
// uhw  sz 16384 hoff 106496
// uow  sz 8192  hoff 139264
// v1w  sz 16384 hoff 155648
// v2w  sz 32768 hoff 188416
#define WPK_TOTAL 126976

// ---------------- dones dtype detection + canonicalization --------------------
__global__ void detect_dones_kernel(const unsigned char* __restrict__ p, int n)
{
    __shared__ int s_nonbin, s_off4;
    if (threadIdx.x == 0) { s_nonbin = 0; s_off4 = 0; }
    __syncthreads();
    int nb = 0, o4 = 0;
    for (int i = threadIdx.x; i < n; i += blockDim.x) {
        const unsigned char b = p[i];
        if (b > 1) nb = 1;
        else if (b == 1 && (i & 3)) o4 = 1;
    }
    if (nb) atomicOr(&s_nonbin, 1);
    if (o4) atomicOr(&s_off4, 1);
    __syncthreads();
    if (threadIdx.x == 0)
        g_dflag = s_nonbin ? 1 : (s_off4 ? 0 : 2);
}

__global__ void conv_dones_kernel(const void* __restrict__ p, int n)
{
    const int i = blockIdx.x * blockDim.x + threadIdx.x;
    if (i >= n) return;
    const int f = g_dflag;
    unsigned char m;
    if (f == 1)      m = (((const float*)p)[i] != 0.f);
    else if (f == 2) m = (((const int*)p)[i] != 0);
    else             m = (((const unsigned char*)p)[i] != 0);
    g_dmask[i] = m;
}

// ---------------- bf16 helpers -------------------------------------------------
__device__ __forceinline__ unsigned pack_bf16(float lo_elem, float hi_elem)
{
    unsigned d;
    asm("cvt.rn.bf16x2.f32 %0, %1, %2;" : "=r"(d) : "f"(hi_elem), "f"(lo_elem));
    return d;
}

__device__ __forceinline__ float bf16hi(float x)
{
    return __bfloat162float(__float2bfloat16(x));
}

// ---------------- one-time weight packing --------------------------------------
// For each weight W[K][N]: packed[kp][n] = bf16x2(W[2kp][n], W[2kp+1][n]) hi + lo
__global__ void pack_weights_kernel(
    const float* __restrict__ s0, const float* __restrict__ s1,
    const float* __restrict__ s2, const float* __restrict__ s3,
    const float* __restrict__ s4, const float* __restrict__ s5,
    const float* __restrict__ s6, const float* __restrict__ s7)
{
    const int idx = blockIdx.x * blockDim.x + threadIdx.x;
    if (idx >= WPK_TOTAL) return;
    const int cum[9]  = {0, 4096, 12288, 36864, 53248, 69632, 77824, 94208, 126976};
    const int hoff[8] = {0, 8192, 24576, 73728, 106496, 139264, 155648, 188416};
    const int Ns[8]   = {128, 128, 384, 128, 128, 128, 256, 256};
    int m = 0;
#pragma unroll
    for (int q = 0; q < 7; q++) if (idx >= cum[q + 1]) m = q + 1;
    const float* srcs[8] = {s0, s1, s2, s3, s4, s5, s6, s7};
    const int local = idx - cum[m];
    const int N = Ns[m];
    const int kp = local / N;
    const int n  = local - kp * N;
    const float* S = srcs[m];
    const float v0 = S[(size_t)(2 * kp) * N + n];
    const float v1 = S[(size_t)(2 * kp + 1) * N + n];
    const float h0 = bf16hi(v0), h1 = bf16hi(v1);
    const int sz = cum[m + 1] - cum[m];
    g_wpk[hoff[m] + local]      = pack_bf16(h0, h1);
    g_wpk[hoff[m] + sz + local] = pack_bf16(v0 - h0, v1 - h1);
}

// ---------------- BF16 tensor-core GEMM (pre-packed weights) -------------------
// C[M,N] = epilogue( A[M,K] @ B[K,N] (+ A2 @ B2) + bias )
// flags: 1 relu | 2 dual-source | 4 resid+alive | 8 B column-split
// B given as packed u32 arrays [K/2][ldb] (hi & lo).
#define BM 128
#define BN 128
#define BK 16
#define AST 12
#define BST 136

__device__ __forceinline__ void mma_bf16(float* c, const unsigned* a, const unsigned* b)
{
    asm volatile(
        "mma.sync.aligned.m16n8k16.row.col.f32.bf16.bf16.f32 "
        "{%0,%1,%2,%3}, {%4,%5,%6,%7}, {%8,%9}, {%0,%1,%2,%3};"
        : "+f"(c[0]), "+f"(c[1]), "+f"(c[2]), "+f"(c[3])
        : "r"(a[0]), "r"(a[1]), "r"(a[2]), "r"(a[3]), "r"(b[0]), "r"(b[1]));
}

__device__ __forceinline__ void ldsm_x4(unsigned& r0, unsigned& r1, unsigned& r2,
                                        unsigned& r3, unsigned addr)
{
    asm volatile("ldmatrix.sync.aligned.m8n8.x4.shared.b16 {%0,%1,%2,%3}, [%4];"
                 : "=r"(r0), "=r"(r1), "=r"(r2), "=r"(r3) : "r"(addr));
}

__global__ __launch_bounds__(256) void tgemm_kernel(
    int M, int N, int K, int ldb,
    const float* __restrict__ A, const float* __restrict__ A2,
    const unsigned* __restrict__ Bmh, const unsigned* __restrict__ Bml,
    const unsigned* __restrict__ B2h, const unsigned* __restrict__ B2l,
    const float* __restrict__ bias, float* __restrict__ Cout,
    int flags, const float* __restrict__ Ein,
    const unsigned char* __restrict__ dones)
{
    __shared__ __align__(16) unsigned As[2][2][BM * AST];
    __shared__ __align__(16) unsigned Bs[2][2][(BK / 2) * BST];

    const int tid  = threadIdx.x;
    const int brow = blockIdx.y * BM;
    const int bcol = blockIdx.x * BN;
    const int w    = tid >> 5, lane = tid & 31;
    const int gid  = lane >> 2, tig = lane & 3;
    const int wm   = (w & 1) * 64;
    const int wn   = (w >> 1) * 32;

    const int arow0 = tid >> 2;
    const int brw   = tid >> 5;
    const int bfc   = (tid & 31) * 4;

    const unsigned aSmemBase = (unsigned)__cvta_generic_to_shared(&As[0][0][0]);
    const unsigned laneOff = ((wm + (lane & 15)) * AST + ((lane & 16) >> 2)) * 4;

    float acc[4][4][4];
#pragma unroll
    for (int i = 0; i < 4; i++)
#pragma unroll
        for (int j = 0; j < 4; j++)
#pragma unroll
            for (int q = 0; q < 4; q++) acc[i][j][q] = 0.f;

    const int nsrc = (flags & 2) ? 2 : 1;
    const int tilesPerSrc = K / BK;
    const int ntiles = nsrc * tilesPerSrc;

    float4 rA[2];
    uint4 rBh, rBl;

    auto loadTile = [&](int t) {
        const int s  = (t >= tilesPerSrc) ? 1 : 0;
        const int k0 = (t - s * tilesPerSrc) * BK;
        const float* Ap = s ? A2 : A;
        const unsigned *Bph, *Bpl;
        int bc;
        if (flags & 8) {
            const bool hi = (bcol >= BN);
            Bph = hi ? B2h : Bmh;  Bpl = hi ? B2l : Bml;  bc = 0;
        } else {
            Bph = s ? B2h : Bmh;   Bpl = s ? B2l : Bml;   bc = bcol;
        }
        const int afc = (tid & 3) * 4;
        rA[0] = *(const float4*)(Ap + (size_t)(brow + arow0) * K + k0 + afc);
        rA[1] = *(const float4*)(Ap + (size_t)(brow + arow0 + 64) * K + k0 + afc);
        const size_t boff = (size_t)(k0 / 2 + brw) * ldb + bc + bfc;
        rBh = *(const uint4*)(Bph + boff);
        rBl = *(const uint4*)(Bpl + boff);
    };

    auto storeTile = [&](int buf) {
#pragma unroll
        for (int p = 0; p < 2; p++) {
            const float4 v = rA[p];
            const float h0 = bf16hi(v.x), h1 = bf16hi(v.y);
            const float h2 = bf16hi(v.z), h3 = bf16hi(v.w);
            const int base = (arow0 + p * 64) * AST + (tid & 3) * 2;
            *(uint2*)&As[buf][0][base] = make_uint2(pack_bf16(h0, h1), pack_bf16(h2, h3));
            *(uint2*)&As[buf][1][base] = make_uint2(pack_bf16(v.x - h0, v.y - h1),
                                                    pack_bf16(v.z - h2, v.w - h3));
        }
        const int base = brw * BST + bfc;
        *(uint4*)&Bs[buf][0][base] = rBh;
        *(uint4*)&Bs[buf][1][base] = rBl;
    };

    loadTile(0);
    storeTile(0);
    __syncthreads();

    for (int t = 0; t < ntiles; t++) {
        if (t + 1 < ntiles) loadTile(t + 1);

        const int cur = t & 1;
        const unsigned* Bsh = Bs[cur][0];
        const unsigned* Bsl = Bs[cur][1];
        const unsigned aTileH = aSmemBase + (unsigned)(cur * (2 * BM * AST * 4)) + laneOff;
        const unsigned aTileL = aTileH + (unsigned)(BM * AST * 4);

        unsigned bh[4][2], bl[4][2];
#pragma unroll
        for (int ns = 0; ns < 4; ns++) {
            const int n = wn + ns * 8 + gid;
            bh[ns][0] = Bsh[tig * BST + n];
            bh[ns][1] = Bsh[(tig + 4) * BST + n];
            bl[ns][0] = Bsl[tig * BST + n];
            bl[ns][1] = Bsl[(tig + 4) * BST + n];
        }
#pragma unroll
        for (int ms = 0; ms < 4; ms++) {
            unsigned ah[4], al[4];
            ldsm_x4(ah[0], ah[1], ah[2], ah[3], aTileH + (unsigned)(ms * 16 * AST * 4));
            ldsm_x4(al[0], al[1], al[2], al[3], aTileL + (unsigned)(ms * 16 * AST * 4));
#pragma unroll
            for (int ns = 0; ns < 4; ns++) {
                mma_bf16(acc[ms][ns], ah, bh[ns]);
                mma_bf16(acc[ms][ns], ah, bl[ns]);
                mma_bf16(acc[ms][ns], al, bh[ns]);
            }
        }

        if (t + 1 < ntiles) {
            storeTile((t + 1) & 1);
            __syncthreads();
        }
    }

    const bool hasb   = (bias != nullptr);
    const bool resid  = (flags & 4);
    const bool dorelu = (flags & 5);
#pragma unroll
    for (int ms = 0; ms < 4; ms++) {
        const int r0 = brow + wm + ms * 16 + gid;
        const int r1 = r0 + 8;
        float alive0 = 1.f, alive1 = 1.f;
        const float *E0 = nullptr, *E1 = nullptr;
        if (resid) {
            alive0 = dones[r0] ? 0.f : 1.f;
            alive1 = dones[r1] ? 0.f : 1.f;
            E0 = Ein + (size_t)r0 * N;
            E1 = Ein + (size_t)r1 * N;
        }
#pragma unroll
        for (int ns = 0; ns < 4; ns++) {
            const int c = bcol + wn + ns * 8 + tig * 2;
            float b0 = 0.f, b1 = 0.f;
            if (hasb) { b0 = bias[c]; b1 = bias[c + 1]; }
            float v0 = acc[ms][ns][0] + b0;
            float v1 = acc[ms][ns][1] + b1;
            float v2 = acc[ms][ns][2] + b0;
            float v3 = acc[ms][ns][3] + b1;
            if (dorelu) {
                v0 = fmaxf(v0, 0.f); v1 = fmaxf(v1, 0.f);
                v2 = fmaxf(v2, 0.f); v3 = fmaxf(v3, 0.f);
            }
            if (resid) {
                v0 = (E0[c] + v0) * alive0;     v1 = (E0[c + 1] + v1) * alive0;
                v2 = (E1[c] + v2) * alive1;     v3 = (E1[c + 1] + v3) * alive1;
            }
            *(float2*)&Cout[(size_t)r0 * N + c] = make_float2(v0, v1);
            *(float2*)&Cout[(size_t)r1 * N + c] = make_float2(v2, v3);
        }
    }
}

// ---------------- persistent GRU scan: regs Wh, f32x2, smem dones --------------
#define RPB 4
#define GTH 384

__device__ __forceinline__ unsigned long long fma_f32x2(
    unsigned long long a, unsigned long long b, unsigned long long c)
{
    unsigned long long d;
    asm("fma.rn.f32x2 %0, %1, %2, %3;" : "=l"(d) : "l"(a), "l"(b), "l"(c));
    return d;
}

__device__ __forceinline__ float sig_fast(float x)
{
    return __fdividef(1.f, 1.f + __expf(-x));
}
__device__ __forceinline__ float tanh_fast(float x)
{
    return __fdividef(2.f, 1.f + __expf(-2.f * x)) - 1.f;
}

__global__ __launch_bounds__(GTH, 1) void gru_kernel(
    const float* __restrict__ gi,
    const unsigned char* __restrict__ dones,
    const float* __restrict__ h0,
    const float* __restrict__ Wh,
    const float* __restrict__ bhn,
    float* __restrict__ e_out,
    float* __restrict__ hidden_out)
{
    __shared__ __align__(16) float hs2[64 * 8];   // [kpair][r*2 + (lo/hi)]
    __shared__ float ghs[RPB * 384];
    __shared__ float sbhn[D];
    __shared__ unsigned char sdn[T_STEPS * RPB];  // dones slice, smem-resident

    const int tid = threadIdx.x;
    const int rowbase = blockIdx.x * RPB;

    unsigned long long w[64];
#pragma unroll
    for (int kp = 0; kp < 64; kp++) {
        const unsigned lo = __float_as_uint(Wh[(size_t)(2 * kp) * 384 + tid]);
        const unsigned hi = __float_as_uint(Wh[(size_t)(2 * kp + 1) * 384 + tid]);
        w[kp] = ((unsigned long long)hi << 32) | lo;
    }
    if (tid < D) sbhn[tid] = bhn[tid];
    if (tid < T_STEPS)
        *(uchar4*)&sdn[tid * 4] = *(const uchar4*)&dones[tid * BATCH + rowbase];

    const int rA = tid >> 7, dA = tid & 127;
    const int rowA = rowbase + rA;
    const bool hasB = (tid < 128);
    const int rowB = rowbase + 3;

    float pa0, pa1, pa2, pb0 = 0.f, pb1 = 0.f, pb2 = 0.f;
    auto prefetch = [&](int t) {
        const size_t gibA = ((size_t)t * BATCH + rowA) * (3 * D);
        pa0 = gi[gibA + dA];
        pa1 = gi[gibA + D + dA];
        pa2 = gi[gibA + 2 * D + dA];
        if (hasB) {
            const size_t gibB = ((size_t)t * BATCH + rowB) * (3 * D);
            pb0 = gi[gibB + tid];
            pb1 = gi[gibB + D + tid];
            pb2 = gi[gibB + 2 * D + tid];
        }
    };

    prefetch(0);
    __syncthreads();   // sdn visible

    for (int idx = tid; idx < RPB * D; idx += GTH) {
        const int r = idx >> 7, d = idx & 127;
        const int row = rowbase + r;
        float v = sdn[r] ? 0.f : h0[(size_t)row * D + d];
        hs2[(d >> 1) * 8 + r * 2 + (d & 1)] = v;
    }
    __syncthreads();

    for (int t = 0; t < T_STEPS; t++) {
        {
            unsigned long long a0 = 0, a1 = 0, a2 = 0, a3 = 0;
#pragma unroll
            for (int kp = 0; kp < 64; kp++) {
                const ulonglong2 p01 = *(const ulonglong2*)(hs2 + kp * 8);
                const ulonglong2 p23 = *(const ulonglong2*)(hs2 + kp * 8 + 4);
                a0 = fma_f32x2(w[kp], p01.x, a0);
                a1 = fma_f32x2(w[kp], p01.y, a1);
                a2 = fma_f32x2(w[kp], p23.x, a2);
                a3 = fma_f32x2(w[kp], p23.y, a3);
            }
            ghs[0 * 384 + tid] = __uint_as_float((unsigned)a0) + __uint_as_float((unsigned)(a0 >> 32));
            ghs[1 * 384 + tid] = __uint_as_float((unsigned)a1) + __uint_as_float((unsigned)(a1 >> 32));
            ghs[2 * 384 + tid] = __uint_as_float((unsigned)a2) + __uint_as_float((unsigned)(a2 >> 32));
            ghs[3 * 384 + tid] = __uint_as_float((unsigned)a3) + __uint_as_float((unsigned)(a3 >> 32));
        }
        __syncthreads();

        {
            {
                const int r = rA, d = dA, row = rowA;
                const float h_r = ghs[r * 384 + d];
                const float h_z = ghs[r * 384 + D + d];
                const float h_n = ghs[r * 384 + 2 * D + d];
                const int hsidx = (d >> 1) * 8 + r * 2 + (d & 1);
                const float hprev = hs2[hsidx];
                const float rg = sig_fast(pa0 + h_r);
                const float zg = sig_fast(pa1 + h_z);
                const float ng = tanh_fast(pa2 + rg * (h_n + sbhn[d]));
                const float hn = (1.f - zg) * ng + zg * hprev;
                const float alive = sdn[t * 4 + r] ? 0.f : 1.f;
                e_out[((size_t)t * BATCH + row) * D + d] = hn * alive;
                if (t == T_STEPS - 1) hidden_out[(size_t)row * D + d] = hn;
                else hs2[hsidx] = sdn[(t + 1) * 4 + r] ? 0.f : hn;
            }
            if (hasB) {
                const int d = tid, row = rowB;
                const float h_r = ghs[3 * 384 + d];
                const float h_z = ghs[3 * 384 + D + d];
                const float h_n = ghs[3 * 384 + 2 * D + d];
                const int hsidx = (d >> 1) * 8 + 3 * 2 + (d & 1);
                const float hprev = hs2[hsidx];
                const float rg = sig_fast(pb0 + h_r);
                const float zg = sig_fast(pb1 + h_z);
                const float ng = tanh_fast(pb2 + rg * (h_n + sbhn[d]));
                const float hn = (1.f - zg) * ng + zg * hprev;
                const float alive = sdn[t * 4 + 3] ? 0.f : 1.f;
                e_out[((size_t)t * BATCH + row) * D + d] = hn * alive;
                if (t == T_STEPS - 1) hidden_out[(size_t)row * D + d] = hn;
                else hs2[hsidx] = sdn[(t + 1) * 4 + 3] ? 0.f : hn;
            }
        }
        if (t + 1 < T_STEPS) prefetch(t + 1);
        __syncthreads();
    }
}

// ---------------- fused pairwise-coupling C + context (lane-parallel j) --------
__global__ __launch_bounds__(256) void couple_ctx_kernel(
    const float* __restrict__ e, const float* __restrict__ aiaj,
    const float* __restrict__ chb,
    const float* __restrict__ cow, const float* __restrict__ cob,
    float* __restrict__ ctx)
{
    __shared__ float sai[NA * 132];
    __shared__ float sajt[128 * 9];
    __shared__ float se[NA * D];
    __shared__ float sb[CH], sw[CH];
    __shared__ float sC[NA * NA];

    const int g  = blockIdx.x;
    const size_t base  = (size_t)g * NA * D;
    const size_t base2 = (size_t)g * NA * 256;
    const int tid = threadIdx.x;
    const int lane = tid & 31, warp = tid >> 5;

    {
        const int j = warp;
        const int k0 = lane * 4;
        const float4 vi = *(const float4*)&aiaj[base2 + j * 256 + k0];
        const float4 vj = *(const float4*)&aiaj[base2 + j * 256 + 128 + k0];
        *(float4*)&sai[j * 132 + k0] = vi;
        sajt[(k0 + 0) * 9 + j] = vj.x;
        sajt[(k0 + 1) * 9 + j] = vj.y;
        sajt[(k0 + 2) * 9 + j] = vj.z;
        sajt[(k0 + 3) * 9 + j] = vj.w;
    }
    *(float4*)&se[tid * 4] = *(const float4*)&e[base + tid * 4];
    if (tid < CH) { sb[tid] = chb[tid]; sw[tid] = cow[tid]; }
    __syncthreads();

    {
        const int i = warp;
        const int jj = lane & 7, slice = lane >> 3;
        const float cb = cob[0];
        float s = 0.f;
#pragma unroll
        for (int it = 0; it < 32; it++) {
            const int kk = slice * 32 + ((it + slice * 8) & 31);
            const float v = sai[i * 132 + kk] + sajt[kk * 9 + jj] + sb[kk];
            s += fmaxf(v, 0.f) * sw[kk];
        }
        s += __shfl_xor_sync(0xffffffffu, s, 8);
        s += __shfl_xor_sync(0xffffffffu, s, 16);
        if (lane < 8)
            sC[i * NA + lane] = (i == lane) ? 0.f : 1.f / (1.f + expf(-(s + cb)));
    }
    __syncthreads();

    for (int idx = tid; idx < NA * D; idx += 256) {
        const int i = idx >> 7, d = idx & 127;
        float s = 0.f;
#pragma unroll
        for (int j = 0; j < NA; j++) s += sC[i * NA + j] * se[j * D + d];
        ctx[base + idx] = s;
    }
}

// ---------------- final value projection (VH -> 1) ------------------------------
__global__ __launch_bounds__(256) void vout_kernel(
    const float* __restrict__ v2, const float* __restrict__ w,
    const float* __restrict__ b, float* __restrict__ out)
{
    __shared__ float sw[VH];
    const int tid = threadIdx.x;
    sw[tid] = w[tid];
    __syncthreads();
    const int warp = tid >> 5, lane = tid & 31;
    const int row = blockIdx.x * 8 + warp;
    const float* vp = v2 + (size_t)row * VH;
    float s = 0.f;
#pragma unroll
    for (int k = lane; k < VH; k += 32) s += vp[k] * sw[k];
#pragma unroll
    for (int off = 16; off; off >>= 1) s += __shfl_xor_sync(0xffffffffu, s, off);
    if (lane == 0) out[row] = s + b[0];
}

// ---------------- launcher -------------------------------------------------------
extern "C" void kernel_launch(void* const* d_in, const int* in_sizes, int n_in,
                              void* d_out, int out_size)
{
    const float* hidden = (const float*)d_in[0];
    const float* obs    = (const float*)d_in[1];
    const void*  dones_raw = d_in[2];
    const float* e1w = (const float*)d_in[3];
    const float* e1b = (const float*)d_in[4];
    const float* e2w = (const float*)d_in[5];
    const float* e2b = (const float*)d_in[6];
    const float* gWi = (const float*)d_in[7];
    const float* gbi = (const float*)d_in[8];
    const float* gWh = (const float*)d_in[9];
    const float* gbhn = (const float*)d_in[10];
    const float* chw = (const float*)d_in[11];
    const float* chb = (const float*)d_in[12];
    const float* cow = (const float*)d_in[13];
    const float* cob = (const float*)d_in[14];
    const float* uhw = (const float*)d_in[15];
    const float* uhb = (const float*)d_in[16];
    const float* uow = (const float*)d_in[17];
    const float* uob = (const float*)d_in[18];
    const float* v1w = (const float*)d_in[19];
    const float* v1b = (const float*)d_in[20];
    const float* v2w = (const float*)d_in[21];
    const float* v2b = (const float*)d_in[22];
    const float* vow = (const float*)d_in[23];
    const float* vob = (const float*)d_in[24];

    float* out_hidden = (float*)d_out;                 // (B, D)
    float* out_values = (float*)d_out + BATCH * D;     // (T, B)

    float *emb1, *emb2, *gi, *e, *aiaj, *ctx, *d1, *v1, *v2;
    unsigned char* dmask;
    unsigned* wpk;
    cudaGetSymbolAddress((void**)&emb1, g_emb1);
    cudaGetSymbolAddress((void**)&emb2, g_emb2);
    cudaGetSymbolAddress((void**)&gi,   g_gi);
    cudaGetSymbolAddress((void**)&e,    g_e);
    cudaGetSymbolAddress((void**)&aiaj, g_aiaj);
    cudaGetSymbolAddress((void**)&ctx,  g_ctx);
    cudaGetSymbolAddress((void**)&d1,   g_d1);
    cudaGetSymbolAddress((void**)&v1,   g_v1);
    cudaGetSymbolAddress((void**)&v2,   g_v2);
    cudaGetSymbolAddress((void**)&dmask, g_dmask);
    cudaGetSymbolAddress((void**)&wpk,  g_wpk);

    // packed weight pointers (hi; lo = hi + sz)
    unsigned* e1wP = wpk + 0;        // sz 4096
    unsigned* e2wP = wpk + 8192;     // sz 8192
    unsigned* gWiP = wpk + 24576;    // sz 24576
    unsigned* chwP = wpk + 73728;    // sz 16384 (W1 kp 0-63, W2 kp 64-127)
    unsigned* uhwP = wpk + 106496;   // sz 16384 (U1 kp 0-63, U2 kp 64-127)
    unsigned* uowP = wpk + 139264;   // sz 8192
    unsigned* v1wP = wpk + 155648;   // sz 16384
    unsigned* v2wP = wpk + 188416;   // sz 32768

    const int M = TB;
    const dim3 blk(256);

    detect_dones_kernel<<<1, 256>>>((const unsigned char*)dones_raw, TB);
    conv_dones_kernel<<<TB / 256, 256>>>(dones_raw, TB);
    pack_weights_kernel<<<(WPK_TOTAL + 255) / 256, 256>>>(
        e1w, e2w, gWi, chw, uhw, uow, v1w, v2w);

    // embed1: relu(obs @ e1w + e1b)
    tgemm_kernel<<<dim3(D / BN, M / BM), blk>>>(M, D, OBS, D, obs, nullptr,
        e1wP, e1wP + 4096, nullptr, nullptr, e1b, emb1, 1, nullptr, nullptr);
    // embed2: relu(emb1 @ e2w + e2b)
    tgemm_kernel<<<dim3(D / BN, M / BM), blk>>>(M, D, D, D, emb1, nullptr,
        e2wP, e2wP + 8192, nullptr, nullptr, e2b, emb2, 1, nullptr, nullptr);
    // gi = emb2 @ gWi + gbi
    tgemm_kernel<<<dim3(3 * D / BN, M / BM), blk>>>(M, 3 * D, D, 3 * D, emb2, nullptr,
        gWiP, gWiP + 24576, nullptr, nullptr, gbi, gi, 0, nullptr, nullptr);
    // sequential GRU scan
    gru_kernel<<<BATCH / RPB, GTH>>>(gi, dmask, hidden, gWh, gbhn, e, out_hidden);

    for (int it = 0; it < ITERS; it++) {
        // [ai | aj] = e @ [W1 | W2]   (col-split: W2 = chw kpairs 64-127)
        tgemm_kernel<<<dim3(2 * CH / BN, M / BM), blk>>>(M, 2 * CH, D, CH, e, nullptr,
            chwP, chwP + 16384, chwP + 8192, chwP + 16384 + 8192,
            nullptr, aiaj, 8, nullptr, nullptr);
        couple_ctx_kernel<<<T_STEPS * NE, 256>>>(e, aiaj, chb, cow, cob, ctx);
        // d1 = relu(e @ U1 + ctx @ U2 + uhb)
        tgemm_kernel<<<dim3(D / BN, M / BM), blk>>>(M, D, D, D, e, ctx,
            uhwP, uhwP + 16384, uhwP + 8192, uhwP + 16384 + 8192,
            uhb, d1, 1 | 2, nullptr, nullptr);
        // e = (e + relu(d1 @ uow + uob)) * alive   (in place)
        tgemm_kernel<<<dim3(D / BN, M / BM), blk>>>(M, D, D, D, d1, nullptr,
            uowP, uowP + 8192, nullptr, nullptr, uob, e, 4, e, dmask);
    }

    // value head
    tgemm_kernel<<<dim3(VH / BN, M / BM), blk>>>(M, VH, D, VH, e, nullptr,
        v1wP, v1wP + 16384, nullptr, nullptr, v1b, v1, 1, nullptr, nullptr);
    tgemm_kernel<<<dim3(VH / BN, M / BM), blk>>>(M, VH, VH, VH, v1, nullptr,
        v2wP, v2wP + 32768, nullptr, nullptr, v2b, v2, 1, nullptr, nullptr);
    vout_kernel<<<TB / 8, 256>>>(v2, vow, vob, out_values);
}